// round 8
// baseline (speedup 1.0000x reference)
#include <cuda_runtime.h>

#define NN   50000
#define EE   800000
#define CIN  32
#define COUT 32
#define KEXP 4

// Scratch: y[n][k][c] = map(x[n] @ W[k])[c] as order-preserving uint, 25.6 MB
__device__ unsigned int g_y[NN * KEXP * COUT];

// Monotonic float<->uint mapping: atomicMax on u32 == float max.
__device__ __forceinline__ unsigned int mapFloat(float f) {
    int b = __float_as_int(f);
    return (unsigned int)(b ^ ((b >> 31) | 0x80000000));
}
__device__ __forceinline__ float unmapFloat(unsigned int u) {
    unsigned int b = (u & 0x80000000u) ? (u ^ 0x80000000u) : ~u;
    return __uint_as_float(b);
}
#define MAPPED_NEG_INF 0x007fffffu   // map(-inf)

// ---- packed f32x2 helpers (sm_100a) ----
__device__ __forceinline__ unsigned long long fma2(
    unsigned long long a, unsigned long long b, unsigned long long c) {
    unsigned long long d;
    asm("fma.rn.f32x2 %0, %1, %2, %3;" : "=l"(d) : "l"(a), "l"(b), "l"(c));
    return d;
}
__device__ __forceinline__ unsigned long long packf2(float lo, float hi) {
    unsigned long long d;
    asm("mov.b64 %0, {%1, %2};" : "=l"(d) : "f"(lo), "f"(hi));
    return d;
}
__device__ __forceinline__ void unpackf2(unsigned long long v, float& lo, float& hi) {
    asm("mov.b64 {%0, %1}, %2;" : "=f"(lo), "=f"(hi) : "l"(v));
}

// GEMM: 4 threads per node, one expert each. Weights broadcast from SMEM,
// packed f32x2 math. acc = 16 ull -> ~80 regs -> 2x occupancy vs 1-thread/node.
// Also inits out rows to mapped -inf.
__global__ __launch_bounds__(256) void gemm_kernel(
    const float* __restrict__ x, const float* __restrict__ ew,
    unsigned int* __restrict__ out)
{
    __shared__ float4 sw4[KEXP * CIN * 8];   // raw copy of ew, float4 view
    int tid = threadIdx.x;
    #pragma unroll
    for (int r = 0; r < 4; r++)
        sw4[r * 256 + tid] = ((const float4*)ew)[r * 256 + tid];

    // coalesced init of this block's out span to mapped -inf (NN*8 uint4 total)
    {
        uint4 neg = make_uint4(MAPPED_NEG_INF, MAPPED_NEG_INF, MAPPED_NEG_INF, MAPPED_NEG_INF);
        int start = blockIdx.x * 512;            // 2 uint4 per thread
        #pragma unroll
        for (int r = 0; r < 2; r++) {
            int idx = start + r * 256 + tid;
            if (idx < NN * 8) ((uint4*)out)[idx] = neg;
        }
    }
    __syncthreads();

    int g = blockIdx.x * 256 + tid;
    int n = g >> 2;
    int k = g & 3;
    if (n >= NN) return;

    float xv[CIN];
    const float4* xp4 = (const float4*)(x + n * CIN);   // 4 lanes dedup in L1
    #pragma unroll
    for (int i4 = 0; i4 < 8; i4++) {
        float4 v = xp4[i4];
        xv[i4 * 4] = v.x; xv[i4 * 4 + 1] = v.y; xv[i4 * 4 + 2] = v.z; xv[i4 * 4 + 3] = v.w;
    }

    const ulonglong2* swp = (const ulonglong2*)sw4;
    unsigned long long acc[16];
    #pragma unroll
    for (int t = 0; t < 16; t++) acc[t] = 0ull;
    #pragma unroll
    for (int i = 0; i < CIN; i++) {
        unsigned long long xp = packf2(xv[i], xv[i]);
        #pragma unroll
        for (int c4 = 0; c4 < 8; c4++) {
            ulonglong2 w = swp[k * 256 + i * 8 + c4];   // broadcast per k-group
            acc[c4 * 2]     = fma2(xp, w.x, acc[c4 * 2]);
            acc[c4 * 2 + 1] = fma2(xp, w.y, acc[c4 * 2 + 1]);
        }
    }
    unsigned int* yp = &g_y[(n * KEXP + k) * COUT];
    #pragma unroll
    for (int c4 = 0; c4 < 8; c4++) {
        float f0, f1, f2, f3;
        unpackf2(acc[c4 * 2],     f0, f1);
        unpackf2(acc[c4 * 2 + 1], f2, f3);
        ((uint4*)yp)[c4] = make_uint4(mapFloat(f0), mapFloat(f1), mapFloat(f2), mapFloat(f3));
    }
}

// Edge phase (R3-proven form): lane-per-edge gate; warp sweeps its 32 edges:
// broadcast offsets, one coalesced 128B LDG + one coalesced RED.MAX.U32/edge.
__global__ __launch_bounds__(256) void edge_kernel(
    const float* __restrict__ pos, const int* __restrict__ edge_index,
    const float* __restrict__ gw, const float* __restrict__ gb,
    unsigned int* __restrict__ out)
{
    float g0x = gw[0], g0y = gw[1], g1x = gw[2], g1y = gw[3];
    float g2x = gw[4], g2y = gw[5], g3x = gw[6], g3y = gw[7];
    float b0 = gb[0], b1 = gb[1], b2 = gb[2], b3 = gb[3];

    int tid   = threadIdx.x;
    int lane  = tid & 31;
    int gwarp = (blockIdx.x * blockDim.x + tid) >> 5;
    int nwarp = (gridDim.x * blockDim.x) >> 5;

    for (int base = gwarp * 32; base < EE; base += nwarp * 32) {
        int e = base + lane;                       // EE % 32 == 0
        int2 ei = ((const int2*)edge_index)[e];
        int dst = ei.x, src = ei.y;

        float dx = pos[src * 3]     - pos[dst * 3];
        float dy = pos[src * 3 + 1] - pos[dst * 3 + 1];

        float l0 = fmaf(dx, g0x, fmaf(dy, g0y, b0));
        float l1 = fmaf(dx, g1x, fmaf(dy, g1y, b1));
        float l2 = fmaf(dx, g2x, fmaf(dy, g2y, b2));
        float l3 = fmaf(dx, g3x, fmaf(dy, g3y, b3));
        int bk = 0; float best = l0;
        if (l1 > best) { best = l1; bk = 1; }
        if (l2 > best) { best = l2; bk = 2; }
        if (l3 > best) { best = l3; bk = 3; }

        int yoff = src * (KEXP * COUT) + bk * COUT;
        int doff = dst * COUT;

        #pragma unroll
        for (int j = 0; j < 32; j++) {
            int yo  = __shfl_sync(0xffffffffu, yoff, j);
            int doo = __shfl_sync(0xffffffffu, doff, j);
            unsigned int m = g_y[yo + lane];          // 1 coalesced 128B line
            atomicMax(&out[doo + lane], m);           // 1 coalesced RED line
        }
    }
}

// MLP (R3-proven): thread-per-node, float4 scalar FMA, weights broadcast from
// SMEM. Reads mapped uints from out, unmaps, rewrites floats.
__global__ __launch_bounds__(128) void mlp_kernel(
    const float* __restrict__ w1, const float* __restrict__ w2,
    float* __restrict__ out)
{
    __shared__ float4 s1t[CIN * 16];   // s1t[i*16+j4].k = w1[(j4*4+k)*32 + i]
    __shared__ float4 s2t[64 * 8];     // s2t[j*8 +c4].k = w2[(c4*4+k)*64 + j]
    int tid = threadIdx.x;
    for (int idx = tid; idx < CIN * 16; idx += blockDim.x) {
        int i = idx >> 4, j4 = idx & 15;
        s1t[idx] = make_float4(w1[(j4 * 4 + 0) * 32 + i], w1[(j4 * 4 + 1) * 32 + i],
                               w1[(j4 * 4 + 2) * 32 + i], w1[(j4 * 4 + 3) * 32 + i]);
    }
    for (int idx = tid; idx < 64 * 8; idx += blockDim.x) {
        int j = idx >> 3, c4 = idx & 7;
        s2t[idx] = make_float4(w2[(c4 * 4 + 0) * 64 + j], w2[(c4 * 4 + 1) * 64 + j],
                               w2[(c4 * 4 + 2) * 64 + j], w2[(c4 * 4 + 3) * 64 + j]);
    }
    __syncthreads();

    int n = blockIdx.x * blockDim.x + tid;
    if (n >= NN) return;

    unsigned int* outu = (unsigned int*)out;
    float h[CIN];
    const uint4* inp = (const uint4*)(outu + n * COUT);
    #pragma unroll
    for (int i = 0; i < CIN / 4; i++) {
        uint4 v = inp[i];
        h[i * 4]     = unmapFloat(v.x);
        h[i * 4 + 1] = unmapFloat(v.y);
        h[i * 4 + 2] = unmapFloat(v.z);
        h[i * 4 + 3] = unmapFloat(v.w);
    }

    float o[COUT];
    #pragma unroll
    for (int c = 0; c < COUT; c++) o[c] = h[c];   // skip connection

    #pragma unroll
    for (int j4 = 0; j4 < 16; j4++) {
        float4 acc = make_float4(0.f, 0.f, 0.f, 0.f);
        #pragma unroll
        for (int i = 0; i < CIN; i++) {
            float4 w = s1t[i * 16 + j4];
            acc.x = fmaf(h[i], w.x, acc.x); acc.y = fmaf(h[i], w.y, acc.y);
            acc.z = fmaf(h[i], w.z, acc.z); acc.w = fmaf(h[i], w.w, acc.w);
        }
        float a0 = fmaxf(acc.x, 0.f), a1 = fmaxf(acc.y, 0.f);
        float a2 = fmaxf(acc.z, 0.f), a3 = fmaxf(acc.w, 0.f);
        int j = j4 * 4;
        #pragma unroll
        for (int c4 = 0; c4 < 8; c4++) {
            float4 wA = s2t[(j + 0) * 8 + c4];
            float4 wB = s2t[(j + 1) * 8 + c4];
            float4 wC = s2t[(j + 2) * 8 + c4];
            float4 wD = s2t[(j + 3) * 8 + c4];
            o[c4*4+0] = fmaf(a0, wA.x, fmaf(a1, wB.x, fmaf(a2, wC.x, fmaf(a3, wD.x, o[c4*4+0]))));
            o[c4*4+1] = fmaf(a0, wA.y, fmaf(a1, wB.y, fmaf(a2, wC.y, fmaf(a3, wD.y, o[c4*4+1]))));
            o[c4*4+2] = fmaf(a0, wA.z, fmaf(a1, wB.z, fmaf(a2, wC.z, fmaf(a3, wD.z, o[c4*4+2]))));
            o[c4*4+3] = fmaf(a0, wA.w, fmaf(a1, wB.w, fmaf(a2, wC.w, fmaf(a3, wD.w, o[c4*4+3]))));
        }
    }

    float4* op = (float4*)(out + n * COUT);
    #pragma unroll
    for (int c4 = 0; c4 < 8; c4++)
        op[c4] = make_float4(o[c4*4], o[c4*4+1], o[c4*4+2], o[c4*4+3]);
}

extern "C" void kernel_launch(void* const* d_in, const int* in_sizes, int n_in,
                              void* d_out, int out_size) {
    const float* x          = (const float*)d_in[0];
    const float* pos        = (const float*)d_in[1];
    const int*   edge_index = (const int*)  d_in[2];
    const float* ew         = (const float*)d_in[3];
    const float* gw         = (const float*)d_in[4];
    const float* gb         = (const float*)d_in[5];
    const float* w1         = (const float*)d_in[6];
    const float* w2         = (const float*)d_in[7];

    gemm_kernel<<<(NN * 4 + 255) / 256, 256>>>(x, ew, (unsigned int*)d_out);
    edge_kernel<<<3125, 256>>>(pos, edge_index, gw, gb, (unsigned int*)d_out);
    mlp_kernel<<<(NN + 127) / 128, 128>>>(w1, w2, (float*)d_out);
}

// round 10
// speedup vs baseline: 2.1443x; 2.1443x over previous
#include <cuda_runtime.h>

#define NN   50000
#define EE   800000
#define CIN  32
#define COUT 32
#define KEXP 4

// Scratch: y[n][k][c] = map(x[n] @ W[k])[c] as order-preserving uint, 25.6 MB
__device__ unsigned int g_y[NN * KEXP * COUT];
// Packed 2-D positions for the edge gate (built in gemm_kernel)
__device__ float2 g_pos2[NN];

// Monotonic float<->uint mapping: atomicMax on u32 == float max.
__device__ __forceinline__ unsigned int mapFloat(float f) {
    int b = __float_as_int(f);
    return (unsigned int)(b ^ ((b >> 31) | 0x80000000));
}
__device__ __forceinline__ float unmapFloat(unsigned int u) {
    unsigned int b = (u & 0x80000000u) ? (u ^ 0x80000000u) : ~u;
    return __uint_as_float(b);
}
#define MAPPED_NEG_INF 0x007fffffu   // map(-inf)

// ---- packed f32x2 helpers (sm_100a) ----
__device__ __forceinline__ unsigned long long fma2(
    unsigned long long a, unsigned long long b, unsigned long long c) {
    unsigned long long d;
    asm("fma.rn.f32x2 %0, %1, %2, %3;" : "=l"(d) : "l"(a), "l"(b), "l"(c));
    return d;
}
__device__ __forceinline__ unsigned long long packf2(float lo, float hi) {
    unsigned long long d;
    asm("mov.b64 %0, {%1, %2};" : "=l"(d) : "f"(lo), "f"(hi));
    return d;
}
__device__ __forceinline__ void unpackf2(unsigned long long v, float& lo, float& hi) {
    asm("mov.b64 {%0, %1}, %2;" : "=f"(lo), "=f"(hi) : "l"(v));
}

// GEMM: warp-uniform expert k, 2 nodes per thread (64 nodes per warp-tile).
// All lanes read the SAME weight address (true broadcast, no conflicts) and
// each weight load is amortized over 2 nodes -> half the LDS wavefronts of R5.
// Also inits out rows to mapped -inf and builds g_pos2.
__global__ __launch_bounds__(256) void gemm_kernel(
    const float* __restrict__ x, const float* __restrict__ ew,
    const float* __restrict__ pos, unsigned int* __restrict__ out)
{
    __shared__ float4 sw4[KEXP * CIN * 8];   // raw copy of ew, float4 view
    int tid = threadIdx.x;
    #pragma unroll
    for (int r = 0; r < 4; r++)
        sw4[r * 256 + tid] = ((const float4*)ew)[r * 256 + tid];

    // coalesced init of out to mapped -inf (NN*8 uint4 total)
    {
        uint4 neg = make_uint4(MAPPED_NEG_INF, MAPPED_NEG_INF, MAPPED_NEG_INF, MAPPED_NEG_INF);
        int start = blockIdx.x * 1024;
        #pragma unroll
        for (int r = 0; r < 4; r++) {
            int idx = start + r * 256 + tid;
            if (idx < NN * 8) ((uint4*)out)[idx] = neg;
        }
    }
    __syncthreads();

    int lane  = tid & 31;
    int gwarp = (blockIdx.x * 256 + tid) >> 5;   // 0..3127
    int b = gwarp >> 2;                          // 64-node block
    int k = gwarp & 3;                           // warp-uniform expert
    int n0 = b * 64 + lane;
    int n1 = n0 + 32;
    bool v0 = n0 < NN, v1 = n1 < NN;

    if (k == 0) {   // build packed pos once per node
        if (v0) g_pos2[n0] = make_float2(pos[n0 * 3], pos[n0 * 3 + 1]);
        if (v1) g_pos2[n1] = make_float2(pos[n1 * 3], pos[n1 * 3 + 1]);
    }

    const ulonglong2* swp = (const ulonglong2*)sw4 + k * 256;
    unsigned long long acc0[16], acc1[16];
    #pragma unroll
    for (int t = 0; t < 16; t++) { acc0[t] = 0ull; acc1[t] = 0ull; }

    const float4* xq0 = (const float4*)(x + n0 * CIN);
    const float4* xq1 = (const float4*)(x + n1 * CIN);
    float4 z4 = make_float4(0.f, 0.f, 0.f, 0.f);

    #pragma unroll
    for (int i4 = 0; i4 < 8; i4++) {
        float4 a0 = v0 ? xq0[i4] : z4;
        float4 a1 = v1 ? xq1[i4] : z4;
        float f0[4] = {a0.x, a0.y, a0.z, a0.w};
        float f1[4] = {a1.x, a1.y, a1.z, a1.w};
        #pragma unroll
        for (int ii = 0; ii < 4; ii++) {
            unsigned long long xp0 = packf2(f0[ii], f0[ii]);
            unsigned long long xp1 = packf2(f1[ii], f1[ii]);
            int i = i4 * 4 + ii;
            #pragma unroll
            for (int c4 = 0; c4 < 8; c4++) {
                ulonglong2 w = swp[i * 8 + c4];   // uniform addr -> broadcast
                acc0[c4 * 2]     = fma2(xp0, w.x, acc0[c4 * 2]);
                acc0[c4 * 2 + 1] = fma2(xp0, w.y, acc0[c4 * 2 + 1]);
                acc1[c4 * 2]     = fma2(xp1, w.x, acc1[c4 * 2]);
                acc1[c4 * 2 + 1] = fma2(xp1, w.y, acc1[c4 * 2 + 1]);
            }
        }
    }

    if (v0) {
        unsigned int* yp = &g_y[(n0 * KEXP + k) * COUT];
        #pragma unroll
        for (int c4 = 0; c4 < 8; c4++) {
            float f0, f1, f2, f3;
            unpackf2(acc0[c4 * 2],     f0, f1);
            unpackf2(acc0[c4 * 2 + 1], f2, f3);
            ((uint4*)yp)[c4] = make_uint4(mapFloat(f0), mapFloat(f1), mapFloat(f2), mapFloat(f3));
        }
    }
    if (v1) {
        unsigned int* yp = &g_y[(n1 * KEXP + k) * COUT];
        #pragma unroll
        for (int c4 = 0; c4 < 8; c4++) {
            float f0, f1, f2, f3;
            unpackf2(acc1[c4 * 2],     f0, f1);
            unpackf2(acc1[c4 * 2 + 1], f2, f3);
            ((uint4*)yp)[c4] = make_uint4(mapFloat(f0), mapFloat(f1), mapFloat(f2), mapFloat(f3));
        }
    }
}

// Edge phase (R3-proven form): lane-per-edge gate from packed pos2; warp
// sweeps its 32 edges: broadcast offsets, one coalesced 128B LDG + one
// coalesced RED.MAX.U32 per edge.
__global__ __launch_bounds__(256) void edge_kernel(
    const int* __restrict__ edge_index,
    const float* __restrict__ gw, const float* __restrict__ gb,
    unsigned int* __restrict__ out)
{
    float g0x = gw[0], g0y = gw[1], g1x = gw[2], g1y = gw[3];
    float g2x = gw[4], g2y = gw[5], g3x = gw[6], g3y = gw[7];
    float b0 = gb[0], b1 = gb[1], b2 = gb[2], b3 = gb[3];

    int tid   = threadIdx.x;
    int lane  = tid & 31;
    int gwarp = (blockIdx.x * blockDim.x + tid) >> 5;
    int nwarp = (gridDim.x * blockDim.x) >> 5;

    for (int base = gwarp * 32; base < EE; base += nwarp * 32) {
        int e = base + lane;                       // EE % 32 == 0
        int2 ei = ((const int2*)edge_index)[e];
        int dst = ei.x, src = ei.y;

        float2 ps = g_pos2[src];                   // 1 scattered LDG.64
        float2 pd = g_pos2[dst];                   // 1 scattered LDG.64
        float dx = ps.x - pd.x;
        float dy = ps.y - pd.y;

        float l0 = fmaf(dx, g0x, fmaf(dy, g0y, b0));
        float l1 = fmaf(dx, g1x, fmaf(dy, g1y, b1));
        float l2 = fmaf(dx, g2x, fmaf(dy, g2y, b2));
        float l3 = fmaf(dx, g3x, fmaf(dy, g3y, b3));
        int bk = 0; float best = l0;
        if (l1 > best) { best = l1; bk = 1; }
        if (l2 > best) { best = l2; bk = 2; }
        if (l3 > best) { best = l3; bk = 3; }

        int yoff = src * (KEXP * COUT) + bk * COUT;
        int doff = dst * COUT;

        #pragma unroll
        for (int j = 0; j < 32; j++) {
            int yo  = __shfl_sync(0xffffffffu, yoff, j);
            int doo = __shfl_sync(0xffffffffu, doff, j);
            unsigned int m = g_y[yo + lane];          // 1 coalesced 128B line
            atomicMax(&out[doo + lane], m);           // 1 coalesced RED line
        }
    }
}

// MLP (R3-proven): thread-per-node, float4 scalar FMA, weights broadcast from
// SMEM. Reads mapped uints from out, unmaps, rewrites floats.
__global__ __launch_bounds__(128) void mlp_kernel(
    const float* __restrict__ w1, const float* __restrict__ w2,
    float* __restrict__ out)
{
    __shared__ float4 s1t[CIN * 16];   // s1t[i*16+j4].k = w1[(j4*4+k)*32 + i]
    __shared__ float4 s2t[64 * 8];     // s2t[j*8 +c4].k = w2[(c4*4+k)*64 + j]
    int tid = threadIdx.x;
    for (int idx = tid; idx < CIN * 16; idx += blockDim.x) {
        int i = idx >> 4, j4 = idx & 15;
        s1t[idx] = make_float4(w1[(j4 * 4 + 0) * 32 + i], w1[(j4 * 4 + 1) * 32 + i],
                               w1[(j4 * 4 + 2) * 32 + i], w1[(j4 * 4 + 3) * 32 + i]);
    }
    for (int idx = tid; idx < 64 * 8; idx += blockDim.x) {
        int j = idx >> 3, c4 = idx & 7;
        s2t[idx] = make_float4(w2[(c4 * 4 + 0) * 64 + j], w2[(c4 * 4 + 1) * 64 + j],
                               w2[(c4 * 4 + 2) * 64 + j], w2[(c4 * 4 + 3) * 64 + j]);
    }
    __syncthreads();

    int n = blockIdx.x * blockDim.x + tid;
    if (n >= NN) return;

    unsigned int* outu = (unsigned int*)out;
    float h[CIN];
    const uint4* inp = (const uint4*)(outu + n * COUT);
    #pragma unroll
    for (int i = 0; i < CIN / 4; i++) {
        uint4 v = inp[i];
        h[i * 4]     = unmapFloat(v.x);
        h[i * 4 + 1] = unmapFloat(v.y);
        h[i * 4 + 2] = unmapFloat(v.z);
        h[i * 4 + 3] = unmapFloat(v.w);
    }

    float o[COUT];
    #pragma unroll
    for (int c = 0; c < COUT; c++) o[c] = h[c];   // skip connection

    #pragma unroll
    for (int j4 = 0; j4 < 16; j4++) {
        float4 acc = make_float4(0.f, 0.f, 0.f, 0.f);
        #pragma unroll
        for (int i = 0; i < CIN; i++) {
            float4 w = s1t[i * 16 + j4];
            acc.x = fmaf(h[i], w.x, acc.x); acc.y = fmaf(h[i], w.y, acc.y);
            acc.z = fmaf(h[i], w.z, acc.z); acc.w = fmaf(h[i], w.w, acc.w);
        }
        float a0 = fmaxf(acc.x, 0.f), a1 = fmaxf(acc.y, 0.f);
        float a2 = fmaxf(acc.z, 0.f), a3 = fmaxf(acc.w, 0.f);
        int j = j4 * 4;
        #pragma unroll
        for (int c4 = 0; c4 < 8; c4++) {
            float4 wA = s2t[(j + 0) * 8 + c4];
            float4 wB = s2t[(j + 1) * 8 + c4];
            float4 wC = s2t[(j + 2) * 8 + c4];
            float4 wD = s2t[(j + 3) * 8 + c4];
            o[c4*4+0] = fmaf(a0, wA.x, fmaf(a1, wB.x, fmaf(a2, wC.x, fmaf(a3, wD.x, o[c4*4+0]))));
            o[c4*4+1] = fmaf(a0, wA.y, fmaf(a1, wB.y, fmaf(a2, wC.y, fmaf(a3, wD.y, o[c4*4+1]))));
            o[c4*4+2] = fmaf(a0, wA.z, fmaf(a1, wB.z, fmaf(a2, wC.z, fmaf(a3, wD.z, o[c4*4+2]))));
            o[c4*4+3] = fmaf(a0, wA.w, fmaf(a1, wB.w, fmaf(a2, wC.w, fmaf(a3, wD.w, o[c4*4+3]))));
        }
    }

    float4* op = (float4*)(out + n * COUT);
    #pragma unroll
    for (int c4 = 0; c4 < 8; c4++)
        op[c4] = make_float4(o[c4*4], o[c4*4+1], o[c4*4+2], o[c4*4+3]);
}

extern "C" void kernel_launch(void* const* d_in, const int* in_sizes, int n_in,
                              void* d_out, int out_size) {
    const float* x          = (const float*)d_in[0];
    const float* pos        = (const float*)d_in[1];
    const int*   edge_index = (const int*)  d_in[2];
    const float* ew         = (const float*)d_in[3];
    const float* gw         = (const float*)d_in[4];
    const float* gb         = (const float*)d_in[5];
    const float* w1         = (const float*)d_in[6];
    const float* w2         = (const float*)d_in[7];

    // 782 node-blocks of 64 -> 3128 warps -> 391 blocks of 256 threads
    gemm_kernel<<<391, 256>>>(x, ew, pos, (unsigned int*)d_out);
    edge_kernel<<<3125, 256>>>(edge_index, gw, gb, (unsigned int*)d_out);
    mlp_kernel<<<(NN + 127) / 128, 128>>>(w1, w2, (float*)d_out);
}

// round 11
// speedup vs baseline: 2.2469x; 1.0478x over previous
#include <cuda_runtime.h>

#define NN   50000
#define EE   800000
#define CIN  32
#define COUT 32
#define KEXP 4

// Scratch: y[n][k][c] = map(x[n] @ W[k])[c] as order-preserving uint, 25.6 MB
__device__ unsigned int g_y[NN * KEXP * COUT];
// Packed 2-D positions for the edge gate (built in gemm_kernel)
__device__ float2 g_pos2[NN];

// Monotonic float<->uint mapping: atomicMax on u32 == float max.
__device__ __forceinline__ unsigned int mapFloat(float f) {
    int b = __float_as_int(f);
    return (unsigned int)(b ^ ((b >> 31) | 0x80000000));
}
__device__ __forceinline__ float unmapFloat(unsigned int u) {
    unsigned int b = (u & 0x80000000u) ? (u ^ 0x80000000u) : ~u;
    return __uint_as_float(b);
}
#define MAPPED_NEG_INF 0x007fffffu   // map(-inf)

// ---- packed f32x2 helpers (sm_100a) ----
__device__ __forceinline__ unsigned long long fma2(
    unsigned long long a, unsigned long long b, unsigned long long c) {
    unsigned long long d;
    asm("fma.rn.f32x2 %0, %1, %2, %3;" : "=l"(d) : "l"(a), "l"(b), "l"(c));
    return d;
}
__device__ __forceinline__ unsigned long long packf2(float lo, float hi) {
    unsigned long long d;
    asm("mov.b64 %0, {%1, %2};" : "=l"(d) : "f"(lo), "f"(hi));
    return d;
}
__device__ __forceinline__ void unpackf2(unsigned long long v, float& lo, float& hi) {
    asm("mov.b64 {%0, %1}, %2;" : "=f"(lo), "=f"(hi) : "l"(v));
}

#define SX_STRIDE 36   // floats per padded x row (4-way max banks)
#define SY_STRIDE 20   // uints per padded y staging row

// GEMM: block = 64-node tile, 8 warps = 4 experts x 2 node-halves.
// All global traffic lane-contiguous: x staged coalesced into SMEM, y written
// via per-warp SMEM transpose. Weights broadcast-read from SMEM.
__global__ __launch_bounds__(256) void gemm_kernel(
    const float* __restrict__ x, const float* __restrict__ ew,
    const float* __restrict__ pos, unsigned int* __restrict__ out)
{
    __shared__ float4 sw4[KEXP * CIN * 8];          // 16 KB raw weights
    __shared__ float  sx[64 * SX_STRIDE];           // 9.2 KB staged x tile
    __shared__ unsigned int sy[8][32 * SY_STRIDE];  // 20 KB y transpose staging

    int tid  = threadIdx.x;
    int lane = tid & 31;
    int w    = tid >> 5;
    int k    = w & 3;          // warp-uniform expert
    int h    = w >> 2;         // node half (0/1)
    int tile = blockIdx.x * 64;

    #pragma unroll
    for (int r = 0; r < 4; r++)
        sw4[r * 256 + tid] = ((const float4*)ew)[r * 256 + tid];

    // coalesced init of this block's out span to mapped -inf
    {
        uint4 neg = make_uint4(MAPPED_NEG_INF, MAPPED_NEG_INF, MAPPED_NEG_INF, MAPPED_NEG_INF);
        int start = blockIdx.x * 512;
        #pragma unroll
        for (int r = 0; r < 2; r++) {
            int idx = start + r * 256 + tid;
            if (idx < NN * 8) ((uint4*)out)[idx] = neg;
        }
    }

    // stage x tile (64 rows x 32 floats), coalesced LDG.128
    #pragma unroll
    for (int rr = 0; rr < 2; rr++) {
        int idx = rr * 256 + tid;          // 0..511
        int row = idx >> 3, c4 = idx & 7;
        int n = tile + row;
        float4 v = make_float4(0.f, 0.f, 0.f, 0.f);
        if (n < NN) v = ((const float4*)x)[n * 8 + c4];
        *(float4*)&sx[row * SX_STRIDE + c4 * 4] = v;
    }

    // build packed pos (k==0 warps cover both halves)
    if (k == 0) {
        int n = tile + h * 32 + lane;
        if (n < NN) g_pos2[n] = make_float2(pos[n * 3], pos[n * 3 + 1]);
    }
    __syncthreads();

    int r = h * 32 + lane;          // my node's row in sx
    const ulonglong2* swp = (const ulonglong2*)sw4 + k * 256;

    unsigned long long acc[16];
    #pragma unroll
    for (int t = 0; t < 16; t++) acc[t] = 0ull;

    #pragma unroll
    for (int i4 = 0; i4 < 8; i4++) {
        float4 a = *(const float4*)&sx[r * SX_STRIDE + i4 * 4];
        float f[4] = {a.x, a.y, a.z, a.w};
        #pragma unroll
        for (int ii = 0; ii < 4; ii++) {
            unsigned long long xp = packf2(f[ii], f[ii]);
            int i = i4 * 4 + ii;
            #pragma unroll
            for (int c4 = 0; c4 < 8; c4++) {
                ulonglong2 wt = swp[i * 8 + c4];     // uniform addr -> broadcast
                acc[c4 * 2]     = fma2(xp, wt.x, acc[c4 * 2]);
                acc[c4 * 2 + 1] = fma2(xp, wt.y, acc[c4 * 2 + 1]);
            }
        }
    }

    // writeback via SMEM transpose, 2 phases of 4 channel-chunks
    unsigned int* syw = sy[w];
    #pragma unroll
    for (int p = 0; p < 2; p++) {
        #pragma unroll
        for (int c4 = 0; c4 < 4; c4++) {
            int cc = p * 4 + c4;
            float f0, f1, f2, f3;
            unpackf2(acc[cc * 2],     f0, f1);
            unpackf2(acc[cc * 2 + 1], f2, f3);
            uint4 m = make_uint4(mapFloat(f0), mapFloat(f1), mapFloat(f2), mapFloat(f3));
            *(uint4*)&syw[lane * SY_STRIDE + c4 * 4] = m;
        }
        __syncwarp();
        #pragma unroll
        for (int rr = 0; rr < 4; rr++) {
            int j  = rr * 8 + (lane >> 2);   // node offset within warp 0..31
            int c4 = lane & 3;               // chunk within phase
            uint4 v = *(const uint4*)&syw[j * SY_STRIDE + c4 * 4];
            int nj = tile + h * 32 + j;
            if (nj < NN)
                ((uint4*)g_y)[nj * 32 + k * 8 + p * 4 + c4] = v;  // 4 lines/instr
        }
        __syncwarp();
    }
}

// Edge phase (R3-proven form): lane-per-edge gate from packed pos2; warp
// sweeps its 32 edges: broadcast offsets, one coalesced 128B LDG + one
// coalesced RED.MAX.U32 per edge.
__global__ __launch_bounds__(256) void edge_kernel(
    const int* __restrict__ edge_index,
    const float* __restrict__ gw, const float* __restrict__ gb,
    unsigned int* __restrict__ out)
{
    float g0x = gw[0], g0y = gw[1], g1x = gw[2], g1y = gw[3];
    float g2x = gw[4], g2y = gw[5], g3x = gw[6], g3y = gw[7];
    float b0 = gb[0], b1 = gb[1], b2 = gb[2], b3 = gb[3];

    int tid   = threadIdx.x;
    int lane  = tid & 31;
    int gwarp = (blockIdx.x * blockDim.x + tid) >> 5;
    int nwarp = (gridDim.x * blockDim.x) >> 5;

    for (int base = gwarp * 32; base < EE; base += nwarp * 32) {
        int e = base + lane;                       // EE % 32 == 0
        int2 ei = ((const int2*)edge_index)[e];
        int dst = ei.x, src = ei.y;

        float2 ps = g_pos2[src];                   // 1 scattered LDG.64
        float2 pd = g_pos2[dst];                   // 1 scattered LDG.64
        float dx = ps.x - pd.x;
        float dy = ps.y - pd.y;

        float l0 = fmaf(dx, g0x, fmaf(dy, g0y, b0));
        float l1 = fmaf(dx, g1x, fmaf(dy, g1y, b1));
        float l2 = fmaf(dx, g2x, fmaf(dy, g2y, b2));
        float l3 = fmaf(dx, g3x, fmaf(dy, g3y, b3));
        int bk = 0; float best = l0;
        if (l1 > best) { best = l1; bk = 1; }
        if (l2 > best) { best = l2; bk = 2; }
        if (l3 > best) { best = l3; bk = 3; }

        int yoff = src * (KEXP * COUT) + bk * COUT;
        int doff = dst * COUT;

        #pragma unroll
        for (int j = 0; j < 32; j++) {
            int yo  = __shfl_sync(0xffffffffu, yoff, j);
            int doo = __shfl_sync(0xffffffffu, doff, j);
            unsigned int m = g_y[yo + lane];          // 1 coalesced 128B line
            atomicMax(&out[doo + lane], m);           // 1 coalesced RED line
        }
    }
}

// MLP (R3-proven): thread-per-node, float4 scalar FMA, weights broadcast from
// SMEM. Reads mapped uints from out, unmaps, rewrites floats.
__global__ __launch_bounds__(128) void mlp_kernel(
    const float* __restrict__ w1, const float* __restrict__ w2,
    float* __restrict__ out)
{
    __shared__ float4 s1t[CIN * 16];   // s1t[i*16+j4].k = w1[(j4*4+k)*32 + i]
    __shared__ float4 s2t[64 * 8];     // s2t[j*8 +c4].k = w2[(c4*4+k)*64 + j]
    int tid = threadIdx.x;
    for (int idx = tid; idx < CIN * 16; idx += blockDim.x) {
        int i = idx >> 4, j4 = idx & 15;
        s1t[idx] = make_float4(w1[(j4 * 4 + 0) * 32 + i], w1[(j4 * 4 + 1) * 32 + i],
                               w1[(j4 * 4 + 2) * 32 + i], w1[(j4 * 4 + 3) * 32 + i]);
    }
    for (int idx = tid; idx < 64 * 8; idx += blockDim.x) {
        int j = idx >> 3, c4 = idx & 7;
        s2t[idx] = make_float4(w2[(c4 * 4 + 0) * 64 + j], w2[(c4 * 4 + 1) * 64 + j],
                               w2[(c4 * 4 + 2) * 64 + j], w2[(c4 * 4 + 3) * 64 + j]);
    }
    __syncthreads();

    int n = blockIdx.x * blockDim.x + tid;
    if (n >= NN) return;

    unsigned int* outu = (unsigned int*)out;
    float h[CIN];
    const uint4* inp = (const uint4*)(outu + n * COUT);
    #pragma unroll
    for (int i = 0; i < CIN / 4; i++) {
        uint4 v = inp[i];
        h[i * 4]     = unmapFloat(v.x);
        h[i * 4 + 1] = unmapFloat(v.y);
        h[i * 4 + 2] = unmapFloat(v.z);
        h[i * 4 + 3] = unmapFloat(v.w);
    }

    float o[COUT];
    #pragma unroll
    for (int c = 0; c < COUT; c++) o[c] = h[c];   // skip connection

    #pragma unroll
    for (int j4 = 0; j4 < 16; j4++) {
        float4 acc = make_float4(0.f, 0.f, 0.f, 0.f);
        #pragma unroll
        for (int i = 0; i < CIN; i++) {
            float4 w = s1t[i * 16 + j4];
            acc.x = fmaf(h[i], w.x, acc.x); acc.y = fmaf(h[i], w.y, acc.y);
            acc.z = fmaf(h[i], w.z, acc.z); acc.w = fmaf(h[i], w.w, acc.w);
        }
        float a0 = fmaxf(acc.x, 0.f), a1 = fmaxf(acc.y, 0.f);
        float a2 = fmaxf(acc.z, 0.f), a3 = fmaxf(acc.w, 0.f);
        int j = j4 * 4;
        #pragma unroll
        for (int c4 = 0; c4 < 8; c4++) {
            float4 wA = s2t[(j + 0) * 8 + c4];
            float4 wB = s2t[(j + 1) * 8 + c4];
            float4 wC = s2t[(j + 2) * 8 + c4];
            float4 wD = s2t[(j + 3) * 8 + c4];
            o[c4*4+0] = fmaf(a0, wA.x, fmaf(a1, wB.x, fmaf(a2, wC.x, fmaf(a3, wD.x, o[c4*4+0]))));
            o[c4*4+1] = fmaf(a0, wA.y, fmaf(a1, wB.y, fmaf(a2, wC.y, fmaf(a3, wD.y, o[c4*4+1]))));
            o[c4*4+2] = fmaf(a0, wA.z, fmaf(a1, wB.z, fmaf(a2, wC.z, fmaf(a3, wD.z, o[c4*4+2]))));
            o[c4*4+3] = fmaf(a0, wA.w, fmaf(a1, wB.w, fmaf(a2, wC.w, fmaf(a3, wD.w, o[c4*4+3]))));
        }
    }

    float4* op = (float4*)(out + n * COUT);
    #pragma unroll
    for (int c4 = 0; c4 < 8; c4++)
        op[c4] = make_float4(o[c4*4], o[c4*4+1], o[c4*4+2], o[c4*4+3]);
}

extern "C" void kernel_launch(void* const* d_in, const int* in_sizes, int n_in,
                              void* d_out, int out_size) {
    const float* x          = (const float*)d_in[0];
    const float* pos        = (const float*)d_in[1];
    const int*   edge_index = (const int*)  d_in[2];
    const float* ew         = (const float*)d_in[3];
    const float* gw         = (const float*)d_in[4];
    const float* gb         = (const float*)d_in[5];
    const float* w1         = (const float*)d_in[6];
    const float* w2         = (const float*)d_in[7];

    gemm_kernel<<<(NN + 63) / 64, 256>>>(x, ew, pos, (unsigned int*)d_out);
    edge_kernel<<<3125, 256>>>(edge_index, gw, gb, (unsigned int*)d_out);
    mlp_kernel<<<(NN + 127) / 128, 128>>>(w1, w2, (float*)d_out);
}